// round 8
// baseline (speedup 1.0000x reference)
#include <cuda_runtime.h>
#include <cuda_bf16.h>
#include <cstdint>

#define BB 1024
#define SS 512
#define TT 48
#define FULL 0xFFFFFFFFu
#define RING 16
#define LEAD (RING - 2)   // 14 steps of prefetch lead

typedef unsigned long long ull;

__device__ double g_scratch[BB];
__device__ unsigned int g_count = 0;
__device__ int g_len[BB];
__device__ int g_perm[BB];

__device__ __forceinline__ ull pack2f(float a, float b) {
    ull r;
    asm("mov.b64 %0, {%1, %2};" : "=l"(r) : "f"(a), "f"(b));
    return r;
}
__device__ __forceinline__ void unpack2f(ull v, float& lo, float& hi) {
    asm("mov.b64 {%0, %1}, %2;" : "=f"(lo), "=f"(hi) : "l"(v));
}
__device__ __forceinline__ void fma2(ull& acc, ull a, ull b) {
    asm("fma.rn.f32x2 %0, %1, %2, %0;" : "+l"(acc) : "l"(a), "l"(b));
}
__device__ __forceinline__ ull add2(ull a, ull b) {
    ull r;
    asm("add.rn.f32x2 %0, %1, %2;" : "=l"(r) : "l"(a), "l"(b));
    return r;
}
__device__ __forceinline__ float hsum2(ull a, ull b) {
    ull u = add2(a, b);
    float lo, hi;
    unpack2f(u, lo, hi);
    return lo + hi;
}
__device__ __forceinline__ float warp_sum_f(float v) {
    #pragma unroll
    for (int o = 16; o; o >>= 1) v += __shfl_xor_sync(FULL, v, o);
    return v;
}
// Predicated cp.async: no BSSY/BSYNC divergence cost.
__device__ __forceinline__ void cp_async16_pred(unsigned dst, const float* src, int go) {
    asm volatile(
        "{\n\t.reg .pred p;\n\t"
        "setp.ne.b32 p, %0, 0;\n\t"
        "@p cp.async.cg.shared.global [%1], [%2], 16;\n\t}"
        :: "r"(go), "r"(dst), "l"(src));
}

// ---------- pre-pass 1: sequence lengths ----------
extern "C" __global__ void __launch_bounds__(128)
len_kernel(const float* __restrict__ mask) {
    const int lane = threadIdx.x & 31;
    const int b = blockIdx.x * 4 + (threadIdx.x >> 5);
    float s = 0.f;
    #pragma unroll
    for (int k = 0; k < SS / 32; k++) s += mask[b * SS + k * 32 + lane];
    s = warp_sum_f(s);
    if (lane == 0) g_len[b] = __float2int_rn(s);
}

// ---------- pre-pass 2: counting sort of batches by length ----------
extern "C" __global__ void __launch_bounds__(512)
sort_kernel() {
    __shared__ int hist[SS + 1];
    const int tid = threadIdx.x;
    for (int i = tid; i <= SS; i += 512) hist[i] = 0;
    __syncthreads();
    for (int b = tid; b < BB; b += 512) atomicAdd(&hist[g_len[b]], 1);
    __syncthreads();
    if (tid == 0) {
        int acc = 0;
        for (int i = 0; i <= SS; i++) { int c = hist[i]; hist[i] = acc; acc += c; }
    }
    __syncthreads();
    for (int b = tid; b < BB; b += 512) {
        int r = atomicAdd(&hist[g_len[b]], 1);
        g_perm[r] = b;
    }
}

// One step of the product-domain recurrence.
// Reads partials from parity (t-1)&1, writes parity t&1.
#define STEP_BODY(pA_, pB_, pC_, M_, ringb_, pbufb_) do {                          \
    const unsigned rb_ = (pbufb_) + (unsigned)(((t - 1) & 1) * 640);               \
    const unsigned wb_ = (pbufb_) + (unsigned)((t & 1) * 640);                     \
    const unsigned ea_ = (ringb_) + (unsigned)((t & (RING - 1)) * 192);            \
    float e0_, e1_, e2_;                                                           \
    asm volatile("ld.shared.f32 %0, [%1];" : "=f"(e0_) : "r"(ea_ + cA4));          \
    asm volatile("ld.shared.f32 %0, [%1];" : "=f"(e1_) : "r"(ea_ + cB4));          \
    asm volatile("ld.shared.f32 %0, [%1];" : "=f"(e2_) : "r"(ea_ + cC4));          \
    float ceA_ = __expf(e0_);                                                      \
    float ceB_ = __expf(e1_);                                                      \
    float ceC_ = __expf(e2_);                                                      \
    if ((t & 3) == 0) {                                                            \
        float r0_, r1_;                                                            \
        asm volatile("ld.shared.f32 %0, [%1];" : "=f"(r0_) : "r"(rb_));            \
        asm volatile("ld.shared.f32 %0, [%1];" : "=f"(r1_) : "r"(rb_ + 320));      \
        float ref_ = r0_ + r1_;                                                    \
        float inv_ = __fdividef(1.f, ref_);                                        \
        ceA_ *= inv_; ceB_ *= inv_; ceC_ *= inv_;                                  \
        M_ += (double)__logf(ref_);                                                \
    }                                                                              \
    ull a0_ = 0ull, a1_ = 0ull, b0_ = 0ull, b1_ = 0ull, c0_ = 0ull, c1_ = 0ull;    \
    const unsigned lo_ = rb_ + rb4;                                                \
    const unsigned hi_ = rb_ + 320u + rb4;                                         \
    _Pragma("unroll")                                                              \
    for (int c = 0; c < 3; c++) {                                                  \
        ull P0, P1, P2, P3, Q0, Q1, Q2, Q3;                                        \
        asm volatile("ld.shared.v2.u64 {%0, %1}, [%2];"                            \
            : "=l"(P0), "=l"(P1) : "r"(lo_ + c * 32));                             \
        asm volatile("ld.shared.v2.u64 {%0, %1}, [%2];"                            \
            : "=l"(P2), "=l"(P3) : "r"(lo_ + c * 32 + 16));                        \
        asm volatile("ld.shared.v2.u64 {%0, %1}, [%2];"                            \
            : "=l"(Q0), "=l"(Q1) : "r"(hi_ + c * 32));                             \
        asm volatile("ld.shared.v2.u64 {%0, %1}, [%2];"                            \
            : "=l"(Q2), "=l"(Q3) : "r"(hi_ + c * 32 + 16));                        \
        ull U0 = add2(P0, Q0);                                                     \
        ull U1 = add2(P1, Q1);                                                     \
        ull U2 = add2(P2, Q2);                                                     \
        ull U3 = add2(P3, Q3);                                                     \
        fma2(a0_, U0, EA[4*c  ]); fma2(b0_, U0, EB[4*c  ]); fma2(c0_, U0, EC[4*c  ]); \
        fma2(a1_, U1, EA[4*c+1]); fma2(b1_, U1, EB[4*c+1]); fma2(c1_, U1, EC[4*c+1]); \
        fma2(a0_, U2, EA[4*c+2]); fma2(b0_, U2, EB[4*c+2]); fma2(c0_, U2, EC[4*c+2]); \
        fma2(a1_, U3, EA[4*c+3]); fma2(b1_, U3, EB[4*c+3]); fma2(c1_, U3, EC[4*c+3]); \
    }                                                                              \
    pA_ = hsum2(a0_, a1_) * ceA_;                                                  \
    pB_ = hsum2(b0_, b1_) * ceB_;                                                  \
    pC_ = hsum2(c0_, c1_) * ceC_;                                                  \
    const unsigned st_ = wb_ + stoff;                                              \
    asm volatile("st.shared.f32 [%0], %1;" :: "r"(st_),       "f"(pA_));           \
    asm volatile("st.shared.f32 [%0], %1;" :: "r"(st_ + 64),  "f"(pB_));           \
    asm volatile("st.shared.f32 [%0], %1;" :: "r"(st_ + 128), "f"(pC_));           \
} while (0)

// 256 blocks x 128 threads: one batch per warp. Warp w of block bid takes
// sorted rank 1023-(4*bid+w): longest batches launch first (wave 1), short
// blocks backfill via work-stealing; the 4 warps of a block have near-equal
// lengths. Typical residency ~2 blocks/SM => 2 warps/SMSP, so each warp's
// chain stalls are filled by its SMSP-mate's independent chain.
extern "C" __global__ void __launch_bounds__(128, 2)
crf_kernel(const float* __restrict__ em,      // [B,S,T]
           const int*   __restrict__ tags,    // [B,S]
           const float* __restrict__ trans,   // [T,T]
           const float* __restrict__ startt,  // [T]
           const float* __restrict__ endt,    // [T]
           float* __restrict__ out)
{
    const int lane = threadIdx.x & 31;
    const int wid  = threadIdx.x >> 5;
    const int rank = BB - 1 - (blockIdx.x * 4 + wid);   // longest first
    const int b    = g_perm[rank];
    const int len  = g_len[b];

    __shared__ __align__(16) float em_s[4][RING][TT];     // per-warp ring
    __shared__ __align__(16) float p_buf[4][2][2][80];    // [warp][parity][half][80]

    const int j     = lane & 15;
    const int half  = lane >> 4;
    const int rbase = half * 24;
    const unsigned cA4 = (unsigned)(j * 4);
    const unsigned cB4 = cA4 + 64u;
    const unsigned cC4 = cA4 + 128u;
    const unsigned rb4 = (unsigned)(rbase * 4);
    const int cA = j, cB = j + 16, cC = j + 32;

    // ---- gold path score ----
    float gold;
    {
        float g = 0.f;
        const long eb = (long)b * SS * TT;
        #pragma unroll 4
        for (int it = 0; it < SS / 32; it++) {
            int t = lane + it * 32;
            if (t < len) {
                int tg = tags[b * SS + t];
                if (t == 0) g += __ldg(&startt[tg]) + __ldg(&em[eb + tg]);
                else {
                    int tp = tags[b * SS + t - 1];
                    g += __ldg(&trans[tg * TT + tp]) + __ldg(&em[eb + (long)t * TT + tg]);
                }
                if (t == len - 1) g += __ldg(&endt[tg]);
            }
        }
        gold = warp_sum_f(g);
    }

    // ---- E = exp(transitions): this lane's 24 rows x 3 columns ----
    ull EA[12], EB[12], EC[12];
    #pragma unroll
    for (int k = 0; k < 12; k++) {
        int r = rbase + 2 * k;
        EA[k] = pack2f(__expf(__ldg(&trans[r * TT + cA])),
                       __expf(__ldg(&trans[(r + 1) * TT + cA])));
        EB[k] = pack2f(__expf(__ldg(&trans[r * TT + cB])),
                       __expf(__ldg(&trans[(r + 1) * TT + cB])));
        EC[k] = pack2f(__expf(__ldg(&trans[r * TT + cC])),
                       __expf(__ldg(&trans[(r + 1) * TT + cC])));
    }

    const float* emp = em + (long)b * SS * TT;

    const unsigned ringb = (unsigned)__cvta_generic_to_shared(&em_s[wid][0][0]);
    const unsigned pbufb = (unsigned)__cvta_generic_to_shared(&p_buf[wid][0][0][0]);
    const unsigned stoff = (unsigned)(half * 320 + j * 4);

    // ---- init at t = 0 (product domain, shifted by column-0 score) ----
    float pA, pB, pC;
    double M;
    {
        float a = __ldg(&startt[cA]) + emp[cA];
        float bb = __ldg(&startt[cB]) + emp[cB];
        float cc = __ldg(&startt[cC]) + emp[cC];
        float r0 = __shfl_sync(FULL, a, 0);
        M = (double)r0;
        pA = (half == 0) ? __expf(a - r0) : 0.f;
        pB = (half == 0) ? __expf(bb - r0) : 0.f;
        pC = (half == 0) ? __expf(cc - r0) : 0.f;
        unsigned s0 = pbufb + stoff;   // parity 0
        asm volatile("st.shared.f32 [%0], %1;" :: "r"(s0),       "f"(pA));
        asm volatile("st.shared.f32 [%0], %1;" :: "r"(s0 + 64),  "f"(pB));
        asm volatile("st.shared.f32 [%0], %1;" :: "r"(s0 + 128), "f"(pC));
    }

    // lanes 0-11 prefetch (one 16B quad each)
    const unsigned pf_dst = ringb + (unsigned)(lane * 16);
    const float*   pf_src = emp + lane * 4;
    const int      lenq   = (lane < 12) ? len : 0;

    // ---- prologue: rows 1..LEAD ----
    #pragma unroll
    for (int s = 1; s <= LEAD; s++) {
        cp_async16_pred(pf_dst + (unsigned)((s & (RING - 1)) * 192),
                        pf_src + (long)s * TT, s < lenq);
        asm volatile("cp.async.commit_group;");
    }

    // ---- forward recurrence ----
    #pragma unroll 1
    for (int t = 1; t < len; t++) {
        int s = t + LEAD;
        cp_async16_pred(pf_dst + (unsigned)((s & (RING - 1)) * 192),
                        pf_src + (long)s * TT, s < lenq);
        asm volatile("cp.async.commit_group;");
        asm volatile("cp.async.wait_group 14;" ::: "memory");
        STEP_BODY(pA, pB, pC, M, ringb, pbufb);
    }
    asm volatile("cp.async.wait_group 0;" ::: "memory");

    // ---- final: fwd = M + log(sum_c p_c * exp(end_c)) ----
    {
        float v = pA * __expf(__ldg(&endt[cA]))
                + pB * __expf(__ldg(&endt[cB]))
                + pC * __expf(__ldg(&endt[cC]));
        float ssum = warp_sum_f(v);
        if (lane == 0)
            g_scratch[b] = M + (double)__logf(ssum) - (double)gold;
    }

    // ---- fused mean: last block reduces ----
    __syncthreads();
    __shared__ bool is_last;
    if (threadIdx.x == 0) {
        __threadfence();
        unsigned r = atomicAdd(&g_count, 1u);
        is_last = (r == gridDim.x - 1);
    }
    __syncthreads();
    if (is_last) {
        __threadfence();
        double s = 0.0;
        for (int i = threadIdx.x; i < BB; i += 128) s += g_scratch[i];
        __shared__ double sh[128];
        sh[threadIdx.x] = s;
        __syncthreads();
        #pragma unroll
        for (int o = 64; o; o >>= 1) {
            if (threadIdx.x < o) sh[threadIdx.x] += sh[threadIdx.x + o];
            __syncthreads();
        }
        if (threadIdx.x == 0) {
            out[0] = (float)(sh[0] / (double)BB);
            g_count = 0;   // reset for next graph replay
        }
    }
}

extern "C" void kernel_launch(void* const* d_in, const int* in_sizes, int n_in,
                              void* d_out, int out_size) {
    const float* em     = (const float*)d_in[0];
    const int*   tags   = (const int*)d_in[1];
    const float* mask   = (const float*)d_in[2];
    const float* trans  = (const float*)d_in[3];
    const float* startt = (const float*)d_in[4];
    const float* endt   = (const float*)d_in[5];
    float* out = (float*)d_out;

    len_kernel<<<BB / 4, 128>>>(mask);
    sort_kernel<<<1, 512>>>();
    crf_kernel<<<BB / 4, 128>>>(em, tags, trans, startt, endt, out);
}

// round 9
// speedup vs baseline: 1.0553x; 1.0553x over previous
#include <cuda_runtime.h>
#include <cuda_bf16.h>
#include <cstdint>

#define BB 1024
#define SS 512
#define TT 48
#define FULL 0xFFFFFFFFu

typedef unsigned long long ull;

__device__ double g_scratch[BB];
__device__ unsigned int g_count = 0;
__device__ int g_len[BB];
__device__ int g_perm[BB];

__device__ __forceinline__ ull pack2f(float a, float b) {
    ull r;
    asm("mov.b64 %0, {%1, %2};" : "=l"(r) : "f"(a), "f"(b));
    return r;
}
__device__ __forceinline__ void unpack2f(ull v, float& lo, float& hi) {
    asm("mov.b64 {%0, %1}, %2;" : "=f"(lo), "=f"(hi) : "l"(v));
}
__device__ __forceinline__ void fma2(ull& acc, ull a, ull b) {
    asm("fma.rn.f32x2 %0, %1, %2, %0;" : "+l"(acc) : "l"(a), "l"(b));
}
__device__ __forceinline__ ull add2(ull a, ull b) {
    ull r;
    asm("add.rn.f32x2 %0, %1, %2;" : "=l"(r) : "l"(a), "l"(b));
    return r;
}
__device__ __forceinline__ float hsum2(ull a, ull b) {
    ull u = add2(a, b);
    float lo, hi;
    unpack2f(u, lo, hi);
    return lo + hi;
}
__device__ __forceinline__ float warp_sum_f(float v) {
    #pragma unroll
    for (int o = 16; o; o >>= 1) v += __shfl_xor_sync(FULL, v, o);
    return v;
}

// ---------- pre-pass 1: sequence lengths ----------
extern "C" __global__ void __launch_bounds__(128)
len_kernel(const float* __restrict__ mask) {
    const int lane = threadIdx.x & 31;
    const int b = blockIdx.x * 4 + (threadIdx.x >> 5);
    float s = 0.f;
    #pragma unroll
    for (int k = 0; k < SS / 32; k++) s += mask[b * SS + k * 32 + lane];
    s = warp_sum_f(s);
    if (lane == 0) g_len[b] = __float2int_rn(s);
}

// ---------- pre-pass 2: counting sort of batches by length ----------
extern "C" __global__ void __launch_bounds__(512)
sort_kernel() {
    __shared__ int hist[SS + 1];
    const int tid = threadIdx.x;
    for (int i = tid; i <= SS; i += 512) hist[i] = 0;
    __syncthreads();
    for (int b = tid; b < BB; b += 512) atomicAdd(&hist[g_len[b]], 1);
    __syncthreads();
    if (tid == 0) {
        int acc = 0;
        for (int i = 0; i <= SS; i++) { int c = hist[i]; hist[i] = acc; acc += c; }
    }
    __syncthreads();
    for (int b = tid; b < BB; b += 512) {
        int r = atomicAdd(&hist[g_len[b]], 1);
        g_perm[r] = b;
    }
}

// One recurrence step. Emissions come from registers (exA_/exB_/exC_).
// RBOFF_/WBOFF_ are compile-time parity byte offsets of the p double-buffer.
// DORESC_: whether this step may rescale (only steps with even t need it).
#define STEPX(pA_, pB_, pC_, M_, exA_, exB_, exC_, RBOFF_, WBOFF_, DORESC_, t_) do { \
    const unsigned rb_ = pbufb + (RBOFF_);                                         \
    const unsigned wb_ = pbufb + (WBOFF_);                                         \
    float ceA_ = __expf(exA_);                                                     \
    float ceB_ = __expf(exB_);                                                     \
    float ceC_ = __expf(exC_);                                                     \
    if (DORESC_ && (((t_) & 3) == 0)) {                                            \
        float r0_, r1_;                                                            \
        asm volatile("ld.shared.f32 %0, [%1];" : "=f"(r0_) : "r"(rb_));            \
        asm volatile("ld.shared.f32 %0, [%1];" : "=f"(r1_) : "r"(rb_ + 320));      \
        float ref_ = r0_ + r1_;                                                    \
        float inv_ = __fdividef(1.f, ref_);                                        \
        ceA_ *= inv_; ceB_ *= inv_; ceC_ *= inv_;                                  \
        M_ += (double)__logf(ref_);                                                \
    }                                                                              \
    ull a0_ = 0ull, a1_ = 0ull, b0_ = 0ull, b1_ = 0ull, c0_ = 0ull, c1_ = 0ull;    \
    const unsigned lo_ = rb_ + rb4;                                                \
    const unsigned hi_ = rb_ + 320u + rb4;                                         \
    _Pragma("unroll")                                                              \
    for (int c = 0; c < 3; c++) {                                                  \
        ull P0, P1, P2, P3, Q0, Q1, Q2, Q3;                                        \
        asm volatile("ld.shared.v2.u64 {%0, %1}, [%2];"                            \
            : "=l"(P0), "=l"(P1) : "r"(lo_ + c * 32));                             \
        asm volatile("ld.shared.v2.u64 {%0, %1}, [%2];"                            \
            : "=l"(P2), "=l"(P3) : "r"(lo_ + c * 32 + 16));                        \
        asm volatile("ld.shared.v2.u64 {%0, %1}, [%2];"                            \
            : "=l"(Q0), "=l"(Q1) : "r"(hi_ + c * 32));                             \
        asm volatile("ld.shared.v2.u64 {%0, %1}, [%2];"                            \
            : "=l"(Q2), "=l"(Q3) : "r"(hi_ + c * 32 + 16));                        \
        ull U0 = add2(P0, Q0);                                                     \
        ull U1 = add2(P1, Q1);                                                     \
        ull U2 = add2(P2, Q2);                                                     \
        ull U3 = add2(P3, Q3);                                                     \
        fma2(a0_, U0, EA[4*c  ]); fma2(b0_, U0, EB[4*c  ]); fma2(c0_, U0, EC[4*c  ]); \
        fma2(a1_, U1, EA[4*c+1]); fma2(b1_, U1, EB[4*c+1]); fma2(c1_, U1, EC[4*c+1]); \
        fma2(a0_, U2, EA[4*c+2]); fma2(b0_, U2, EB[4*c+2]); fma2(c0_, U2, EC[4*c+2]); \
        fma2(a1_, U3, EA[4*c+3]); fma2(b1_, U3, EB[4*c+3]); fma2(c1_, U3, EC[4*c+3]); \
    }                                                                              \
    pA_ = hsum2(a0_, a1_) * ceA_;                                                  \
    pB_ = hsum2(b0_, b1_) * ceB_;                                                  \
    pC_ = hsum2(c0_, c1_) * ceC_;                                                  \
    const unsigned st_ = wb_ + stoff;                                              \
    asm volatile("st.shared.f32 [%0], %1;" :: "r"(st_),       "f"(pA_));           \
    asm volatile("st.shared.f32 [%0], %1;" :: "r"(st_ + 64),  "f"(pB_));           \
    asm volatile("st.shared.f32 [%0], %1;" :: "r"(st_ + 128), "f"(pC_));           \
} while (0)

// clamped 3-column emission load for step s (branchless, always in-bounds)
#define LD3(s_, x_, y_, z_) do {                                                   \
    int r_ = min((s_), len - 1);                                                   \
    const float* p_ = emp + (long)r_ * TT;                                         \
    x_ = __ldg(p_ + cA); y_ = __ldg(p_ + cB); z_ = __ldg(p_ + cC);                 \
} while (0)

// 256 blocks x 128 threads: one batch per warp, sorted longest-first.
// Emissions register-prefetched (no cp.async ring). 4-step unrolled body
// with compile-time p-buffer parities (t stays odd at loop top).
extern "C" __global__ void __launch_bounds__(128)
crf_kernel(const float* __restrict__ em,      // [B,S,T]
           const int*   __restrict__ tags,    // [B,S]
           const float* __restrict__ trans,   // [T,T]
           const float* __restrict__ startt,  // [T]
           const float* __restrict__ endt,    // [T]
           float* __restrict__ out)
{
    const int lane = threadIdx.x & 31;
    const int wid  = threadIdx.x >> 5;
    const int rank = BB - 1 - (blockIdx.x * 4 + wid);   // longest first
    const int b    = g_perm[rank];
    const int len  = g_len[b];

    __shared__ __align__(16) float p_buf[4][2][2][80];  // [warp][parity][half][80]

    const int j     = lane & 15;
    const int half  = lane >> 4;
    const int rbase = half * 24;
    const unsigned rb4 = (unsigned)(rbase * 4);
    const int cA = j, cB = j + 16, cC = j + 32;

    // ---- gold path score ----
    float gold;
    {
        float g = 0.f;
        const long eb = (long)b * SS * TT;
        #pragma unroll 4
        for (int it = 0; it < SS / 32; it++) {
            int t = lane + it * 32;
            if (t < len) {
                int tg = tags[b * SS + t];
                if (t == 0) g += __ldg(&startt[tg]) + __ldg(&em[eb + tg]);
                else {
                    int tp = tags[b * SS + t - 1];
                    g += __ldg(&trans[tg * TT + tp]) + __ldg(&em[eb + (long)t * TT + tg]);
                }
                if (t == len - 1) g += __ldg(&endt[tg]);
            }
        }
        gold = warp_sum_f(g);
    }

    // ---- E = exp(transitions): this lane's 24 rows x 3 columns ----
    ull EA[12], EB[12], EC[12];
    #pragma unroll
    for (int k = 0; k < 12; k++) {
        int r = rbase + 2 * k;
        EA[k] = pack2f(__expf(__ldg(&trans[r * TT + cA])),
                       __expf(__ldg(&trans[(r + 1) * TT + cA])));
        EB[k] = pack2f(__expf(__ldg(&trans[r * TT + cB])),
                       __expf(__ldg(&trans[(r + 1) * TT + cB])));
        EC[k] = pack2f(__expf(__ldg(&trans[r * TT + cC])),
                       __expf(__ldg(&trans[(r + 1) * TT + cC])));
    }

    const float* emp = em + (long)b * SS * TT;

    const unsigned pbufb = (unsigned)__cvta_generic_to_shared(&p_buf[wid][0][0][0]);
    const unsigned stoff = (unsigned)(half * 320 + j * 4);

    // ---- init at t = 0 (product domain, shifted by column-0 score) ----
    float pA, pB, pC;
    double M;
    {
        float a  = __ldg(&startt[cA]) + emp[cA];
        float bb = __ldg(&startt[cB]) + emp[cB];
        float cc = __ldg(&startt[cC]) + emp[cC];
        float r0 = __shfl_sync(FULL, a, 0);
        M = (double)r0;
        pA = (half == 0) ? __expf(a - r0) : 0.f;
        pB = (half == 0) ? __expf(bb - r0) : 0.f;
        pC = (half == 0) ? __expf(cc - r0) : 0.f;
        unsigned s0 = pbufb + stoff;   // parity 0
        asm volatile("st.shared.f32 [%0], %1;" :: "r"(s0),       "f"(pA));
        asm volatile("st.shared.f32 [%0], %1;" :: "r"(s0 + 64),  "f"(pB));
        asm volatile("st.shared.f32 [%0], %1;" :: "r"(s0 + 128), "f"(pC));
    }

    // ---- emission register pipeline: rows t .. t+3 live in e0..e3 ----
    float e0A, e0B, e0C, e1A, e1B, e1C, e2A, e2B, e2C, e3A, e3B, e3C;
    LD3(1, e0A, e0B, e0C);
    LD3(2, e1A, e1B, e1C);
    LD3(3, e2A, e2B, e2C);
    LD3(4, e3A, e3B, e3C);

    int t = 1;   // t stays odd at loop top -> static parities inside the body
    #pragma unroll 1
    for (; t + 3 < len; t += 4) {
        float n0A, n0B, n0C, n1A, n1B, n1C, n2A, n2B, n2C, n3A, n3B, n3C;
        LD3(t + 4, n0A, n0B, n0C);
        LD3(t + 5, n1A, n1B, n1C);
        LD3(t + 6, n2A, n2B, n2C);
        LD3(t + 7, n3A, n3B, n3C);

        STEPX(pA, pB, pC, M, e0A, e0B, e0C,   0u, 640u, 0, t);       // t   (odd)
        STEPX(pA, pB, pC, M, e1A, e1B, e1C, 640u,   0u, 1, t + 1);   // t+1 (even)
        STEPX(pA, pB, pC, M, e2A, e2B, e2C,   0u, 640u, 0, t + 2);   // t+2 (odd)
        STEPX(pA, pB, pC, M, e3A, e3B, e3C, 640u,   0u, 1, t + 3);   // t+3 (even)

        e0A = n0A; e0B = n0B; e0C = n0C;
        e1A = n1A; e1B = n1B; e1C = n1C;
        e2A = n2A; e2B = n2B; e2C = n2C;
        e3A = n3A; e3B = n3B; e3C = n3C;
    }
    // ---- tail: 0..3 steps, parities still static (t odd here) ----
    if (t < len) { STEPX(pA, pB, pC, M, e0A, e0B, e0C,   0u, 640u, 0, t); t++; }
    if (t < len) { STEPX(pA, pB, pC, M, e1A, e1B, e1C, 640u,   0u, 1, t); t++; }
    if (t < len) { STEPX(pA, pB, pC, M, e2A, e2B, e2C,   0u, 640u, 0, t); t++; }

    // ---- final: fwd = M + log(sum_c p_c * exp(end_c)) ----
    {
        float v = pA * __expf(__ldg(&endt[cA]))
                + pB * __expf(__ldg(&endt[cB]))
                + pC * __expf(__ldg(&endt[cC]));
        float ssum = warp_sum_f(v);
        if (lane == 0)
            g_scratch[b] = M + (double)__logf(ssum) - (double)gold;
    }

    // ---- fused mean: last block reduces ----
    __syncthreads();
    __shared__ bool is_last;
    if (threadIdx.x == 0) {
        __threadfence();
        unsigned r = atomicAdd(&g_count, 1u);
        is_last = (r == gridDim.x - 1);
    }
    __syncthreads();
    if (is_last) {
        __threadfence();
        double s = 0.0;
        for (int i = threadIdx.x; i < BB; i += 128) s += g_scratch[i];
        __shared__ double sh[128];
        sh[threadIdx.x] = s;
        __syncthreads();
        #pragma unroll
        for (int o = 64; o; o >>= 1) {
            if (threadIdx.x < o) sh[threadIdx.x] += sh[threadIdx.x + o];
            __syncthreads();
        }
        if (threadIdx.x == 0) {
            out[0] = (float)(sh[0] / (double)BB);
            g_count = 0;   // reset for next graph replay
        }
    }
}

extern "C" void kernel_launch(void* const* d_in, const int* in_sizes, int n_in,
                              void* d_out, int out_size) {
    const float* em     = (const float*)d_in[0];
    const int*   tags   = (const int*)d_in[1];
    const float* mask   = (const float*)d_in[2];
    const float* trans  = (const float*)d_in[3];
    const float* startt = (const float*)d_in[4];
    const float* endt   = (const float*)d_in[5];
    float* out = (float*)d_out;

    len_kernel<<<BB / 4, 128>>>(mask);
    sort_kernel<<<1, 512>>>();
    crf_kernel<<<BB / 4, 128>>>(em, tags, trans, startt, endt, out);
}

// round 10
// speedup vs baseline: 1.1765x; 1.1148x over previous
#include <cuda_runtime.h>
#include <cuda_bf16.h>
#include <cstdint>

#define BB 1024
#define SS 512
#define TT 48
#define FULL 0xFFFFFFFFu
#define NWARP 592          // 148 blocks x 4 warps
#define NPAIR 432          // warps 0..431 run two batches; 432..591 run one

typedef unsigned long long ull;

__device__ double g_scratch[BB];
__device__ unsigned int g_count = 0;
__device__ int g_len[BB];
__device__ int g_perm[BB];

__device__ __forceinline__ ull pack2f(float a, float b) {
    ull r;
    asm("mov.b64 %0, {%1, %2};" : "=l"(r) : "f"(a), "f"(b));
    return r;
}
__device__ __forceinline__ void unpack2f(ull v, float& lo, float& hi) {
    asm("mov.b64 {%0, %1}, %2;" : "=f"(lo), "=f"(hi) : "l"(v));
}
__device__ __forceinline__ void fma2(ull& acc, ull a, ull b) {
    asm("fma.rn.f32x2 %0, %1, %2, %0;" : "+l"(acc) : "l"(a), "l"(b));
}
__device__ __forceinline__ ull add2(ull a, ull b) {
    ull r;
    asm("add.rn.f32x2 %0, %1, %2;" : "=l"(r) : "l"(a), "l"(b));
    return r;
}
__device__ __forceinline__ float hsum2(ull a, ull b) {
    ull u = add2(a, b);
    float lo, hi;
    unpack2f(u, lo, hi);
    return lo + hi;
}
__device__ __forceinline__ float warp_sum_f(float v) {
    #pragma unroll
    for (int o = 16; o; o >>= 1) v += __shfl_xor_sync(FULL, v, o);
    return v;
}

// ---------- fused prepass: lengths (binary search on monotone mask) + sort ----------
extern "C" __global__ void __launch_bounds__(1024)
prep_kernel(const float* __restrict__ mask) {
    const int b = threadIdx.x;          // 1024 threads = 1024 batches
    // mask[b][i] = 1 for i < len (len >= 1), else 0: find len by bisection
    int lo = 0, hi = SS;
    #pragma unroll
    for (int it = 0; it < 9; it++) {    // 2^9 = 512
        int mid = (lo + hi) >> 1;
        bool one = __ldg(&mask[b * SS + mid]) > 0.5f;
        lo = one ? mid : lo;
        hi = one ? hi : mid;
    }
    const int len = lo + 1;
    g_len[b] = len;

    __shared__ int hist[SS + 1];
    if (threadIdx.x <= SS) hist[threadIdx.x] = 0;
    __syncthreads();
    atomicAdd(&hist[len], 1);
    __syncthreads();
    if (threadIdx.x == 0) {
        int acc = 0;
        for (int i = 0; i <= SS; i++) { int c = hist[i]; hist[i] = acc; acc += c; }
    }
    __syncthreads();
    int r = atomicAdd(&hist[len], 1);
    g_perm[r] = b;                      // ascending by length
}

// One recurrence step. Emissions come from registers (exA_/exB_/exC_).
// RBOFF_/WBOFF_ are compile-time parity byte offsets of the p double-buffer.
// DORESC_: whether this step may rescale (only steps with even t need it).
#define STEPX(pA_, pB_, pC_, M_, exA_, exB_, exC_, RBOFF_, WBOFF_, DORESC_, t_) do { \
    const unsigned rb_ = pbufb + (RBOFF_);                                         \
    const unsigned wb_ = pbufb + (WBOFF_);                                         \
    float ceA_ = __expf(exA_);                                                     \
    float ceB_ = __expf(exB_);                                                     \
    float ceC_ = __expf(exC_);                                                     \
    if (DORESC_ && (((t_) & 3) == 0)) {                                            \
        float r0_, r1_;                                                            \
        asm volatile("ld.shared.f32 %0, [%1];" : "=f"(r0_) : "r"(rb_));            \
        asm volatile("ld.shared.f32 %0, [%1];" : "=f"(r1_) : "r"(rb_ + 320));      \
        float ref_ = r0_ + r1_;                                                    \
        float inv_ = __fdividef(1.f, ref_);                                        \
        ceA_ *= inv_; ceB_ *= inv_; ceC_ *= inv_;                                  \
        M_ += (double)__logf(ref_);                                                \
    }                                                                              \
    ull a0_ = 0ull, a1_ = 0ull, b0_ = 0ull, b1_ = 0ull, c0_ = 0ull, c1_ = 0ull;    \
    const unsigned lo_ = rb_ + rb4;                                                \
    const unsigned hi_ = rb_ + 320u + rb4;                                         \
    _Pragma("unroll")                                                              \
    for (int c = 0; c < 3; c++) {                                                  \
        ull P0, P1, P2, P3, Q0, Q1, Q2, Q3;                                        \
        asm volatile("ld.shared.v2.u64 {%0, %1}, [%2];"                            \
            : "=l"(P0), "=l"(P1) : "r"(lo_ + c * 32));                             \
        asm volatile("ld.shared.v2.u64 {%0, %1}, [%2];"                            \
            : "=l"(P2), "=l"(P3) : "r"(lo_ + c * 32 + 16));                        \
        asm volatile("ld.shared.v2.u64 {%0, %1}, [%2];"                            \
            : "=l"(Q0), "=l"(Q1) : "r"(hi_ + c * 32));                             \
        asm volatile("ld.shared.v2.u64 {%0, %1}, [%2];"                            \
            : "=l"(Q2), "=l"(Q3) : "r"(hi_ + c * 32 + 16));                        \
        ull U0 = add2(P0, Q0);                                                     \
        ull U1 = add2(P1, Q1);                                                     \
        ull U2 = add2(P2, Q2);                                                     \
        ull U3 = add2(P3, Q3);                                                     \
        fma2(a0_, U0, EA[4*c  ]); fma2(b0_, U0, EB[4*c  ]); fma2(c0_, U0, EC[4*c  ]); \
        fma2(a1_, U1, EA[4*c+1]); fma2(b1_, U1, EB[4*c+1]); fma2(c1_, U1, EC[4*c+1]); \
        fma2(a0_, U2, EA[4*c+2]); fma2(b0_, U2, EB[4*c+2]); fma2(c0_, U2, EC[4*c+2]); \
        fma2(a1_, U3, EA[4*c+3]); fma2(b1_, U3, EB[4*c+3]); fma2(c1_, U3, EC[4*c+3]); \
    }                                                                              \
    pA_ = hsum2(a0_, a1_) * ceA_;                                                  \
    pB_ = hsum2(b0_, b1_) * ceB_;                                                  \
    pC_ = hsum2(c0_, c1_) * ceC_;                                                  \
    const unsigned st_ = wb_ + stoff;                                              \
    asm volatile("st.shared.f32 [%0], %1;" :: "r"(st_),       "f"(pA_));           \
    asm volatile("st.shared.f32 [%0], %1;" :: "r"(st_ + 64),  "f"(pB_));           \
    asm volatile("st.shared.f32 [%0], %1;" :: "r"(st_ + 128), "f"(pC_));           \
} while (0)

// clamped 3-column emission load for step s (branchless, always in-bounds)
#define LD3(s_, x_, y_, z_) do {                                                   \
    int r_ = min((s_), len - 1);                                                   \
    const float* p_ = emp + (long)r_ * TT;                                         \
    x_ = __ldg(p_ + cA); y_ = __ldg(p_ + cB); z_ = __ldg(p_ + cC);                 \
} while (0)

// 148 blocks x 128 threads: exactly 1 CTA/SM, 1 warp/SMSP -> every warp owns
// its SMSP issue port. Warp k runs perm[1023-k] (long) then, if k < NPAIR,
// perm[k] (short) sequentially: pair sums ~= 512 steps for all paired warps.
extern "C" __global__ void __launch_bounds__(128)
crf_kernel(const float* __restrict__ em,      // [B,S,T]
           const int*   __restrict__ tags,    // [B,S]
           const float* __restrict__ trans,   // [T,T]
           const float* __restrict__ startt,  // [T]
           const float* __restrict__ endt,    // [T]
           float* __restrict__ out)
{
    const int lane = threadIdx.x & 31;
    const int wid  = threadIdx.x >> 5;
    const int k    = blockIdx.x * 4 + wid;      // 0..591

    __shared__ __align__(16) float p_buf[4][2][2][80];  // [warp][parity][half][80]

    const int j     = lane & 15;
    const int half  = lane >> 4;
    const int rbase = half * 24;
    const unsigned rb4 = (unsigned)(rbase * 4);
    const int cA = j, cB = j + 16, cC = j + 32;

    // ---- E = exp(transitions): batch-independent, loaded once ----
    ull EA[12], EB[12], EC[12];
    #pragma unroll
    for (int kk = 0; kk < 12; kk++) {
        int r = rbase + 2 * kk;
        EA[kk] = pack2f(__expf(__ldg(&trans[r * TT + cA])),
                        __expf(__ldg(&trans[(r + 1) * TT + cA])));
        EB[kk] = pack2f(__expf(__ldg(&trans[r * TT + cB])),
                        __expf(__ldg(&trans[(r + 1) * TT + cB])));
        EC[kk] = pack2f(__expf(__ldg(&trans[r * TT + cC])),
                        __expf(__ldg(&trans[(r + 1) * TT + cC])));
    }
    const float eeA = __expf(__ldg(&endt[cA]));
    const float eeB = __expf(__ldg(&endt[cB]));
    const float eeC = __expf(__ldg(&endt[cC]));

    const unsigned pbufb = (unsigned)__cvta_generic_to_shared(&p_buf[wid][0][0][0]);
    const unsigned stoff = (unsigned)(half * 320 + j * 4);

    const int npass = (k < NPAIR) ? 2 : 1;
    #pragma unroll 1
    for (int pass = 0; pass < npass; pass++) {
        const int b   = (pass == 0) ? g_perm[BB - 1 - k] : g_perm[k];
        const int len = g_len[b];
        const float* emp = em + (long)b * SS * TT;

        // ---- gold path score ----
        float gold;
        {
            float g = 0.f;
            const long eb = (long)b * SS * TT;
            #pragma unroll 4
            for (int it = 0; it < SS / 32; it++) {
                int t = lane + it * 32;
                if (t < len) {
                    int tg = tags[b * SS + t];
                    if (t == 0) g += __ldg(&startt[tg]) + __ldg(&em[eb + tg]);
                    else {
                        int tp = tags[b * SS + t - 1];
                        g += __ldg(&trans[tg * TT + tp]) + __ldg(&em[eb + (long)t * TT + tg]);
                    }
                    if (t == len - 1) g += __ldg(&endt[tg]);
                }
            }
            gold = warp_sum_f(g);
        }

        // ---- init at t = 0 (product domain, shifted by column-0 score) ----
        float pA, pB, pC;
        double M;
        {
            float a  = __ldg(&startt[cA]) + emp[cA];
            float bb = __ldg(&startt[cB]) + emp[cB];
            float cc = __ldg(&startt[cC]) + emp[cC];
            float r0 = __shfl_sync(FULL, a, 0);
            M = (double)r0;
            pA = (half == 0) ? __expf(a - r0) : 0.f;
            pB = (half == 0) ? __expf(bb - r0) : 0.f;
            pC = (half == 0) ? __expf(cc - r0) : 0.f;
            unsigned s0 = pbufb + stoff;   // parity 0
            asm volatile("st.shared.f32 [%0], %1;" :: "r"(s0),       "f"(pA));
            asm volatile("st.shared.f32 [%0], %1;" :: "r"(s0 + 64),  "f"(pB));
            asm volatile("st.shared.f32 [%0], %1;" :: "r"(s0 + 128), "f"(pC));
        }

        // ---- emission register pipeline: rows t .. t+3 in e0..e3 ----
        float e0A, e0B, e0C, e1A, e1B, e1C, e2A, e2B, e2C, e3A, e3B, e3C;
        LD3(1, e0A, e0B, e0C);
        LD3(2, e1A, e1B, e1C);
        LD3(3, e2A, e2B, e2C);
        LD3(4, e3A, e3B, e3C);

        int t = 1;   // stays odd at loop top -> static parities in the body
        #pragma unroll 1
        for (; t + 3 < len; t += 4) {
            float n0A, n0B, n0C, n1A, n1B, n1C, n2A, n2B, n2C, n3A, n3B, n3C;
            LD3(t + 4, n0A, n0B, n0C);
            LD3(t + 5, n1A, n1B, n1C);
            LD3(t + 6, n2A, n2B, n2C);
            LD3(t + 7, n3A, n3B, n3C);

            STEPX(pA, pB, pC, M, e0A, e0B, e0C,   0u, 640u, 0, t);
            STEPX(pA, pB, pC, M, e1A, e1B, e1C, 640u,   0u, 1, t + 1);
            STEPX(pA, pB, pC, M, e2A, e2B, e2C,   0u, 640u, 0, t + 2);
            STEPX(pA, pB, pC, M, e3A, e3B, e3C, 640u,   0u, 1, t + 3);

            e0A = n0A; e0B = n0B; e0C = n0C;
            e1A = n1A; e1B = n1B; e1C = n1C;
            e2A = n2A; e2B = n2B; e2C = n2C;
            e3A = n3A; e3B = n3B; e3C = n3C;
        }
        if (t < len) { STEPX(pA, pB, pC, M, e0A, e0B, e0C,   0u, 640u, 0, t); t++; }
        if (t < len) { STEPX(pA, pB, pC, M, e1A, e1B, e1C, 640u,   0u, 1, t); t++; }
        if (t < len) { STEPX(pA, pB, pC, M, e2A, e2B, e2C,   0u, 640u, 0, t); t++; }

        // ---- final: fwd = M + log(sum_c p_c * exp(end_c)) ----
        {
            float v = pA * eeA + pB * eeB + pC * eeC;
            float ssum = warp_sum_f(v);
            if (lane == 0)
                g_scratch[b] = M + (double)__logf(ssum) - (double)gold;
        }
    }

    // ---- fused mean: last block reduces ----
    __syncthreads();
    __shared__ bool is_last;
    if (threadIdx.x == 0) {
        __threadfence();
        unsigned r = atomicAdd(&g_count, 1u);
        is_last = (r == gridDim.x - 1);
    }
    __syncthreads();
    if (is_last) {
        __threadfence();
        double s = 0.0;
        for (int i = threadIdx.x; i < BB; i += 128) s += g_scratch[i];
        __shared__ double sh[128];
        sh[threadIdx.x] = s;
        __syncthreads();
        #pragma unroll
        for (int o = 64; o; o >>= 1) {
            if (threadIdx.x < o) sh[threadIdx.x] += sh[threadIdx.x + o];
            __syncthreads();
        }
        if (threadIdx.x == 0) {
            out[0] = (float)(sh[0] / (double)BB);
            g_count = 0;   // reset for next graph replay
        }
    }
}

extern "C" void kernel_launch(void* const* d_in, const int* in_sizes, int n_in,
                              void* d_out, int out_size) {
    const float* em     = (const float*)d_in[0];
    const int*   tags   = (const int*)d_in[1];
    const float* mask   = (const float*)d_in[2];
    const float* trans  = (const float*)d_in[3];
    const float* startt = (const float*)d_in[4];
    const float* endt   = (const float*)d_in[5];
    float* out = (float*)d_out;

    prep_kernel<<<1, 1024>>>(mask);
    crf_kernel<<<148, 128>>>(em, tags, trans, startt, endt, out);
}

// round 11
// speedup vs baseline: 1.3121x; 1.1152x over previous
#include <cuda_runtime.h>
#include <cuda_bf16.h>
#include <cstdint>

#define BB 1024
#define SS 512
#define TT 48
#define FULL 0xFFFFFFFFu
#define NPAIR 432          // warps 0..431 run two batches; 432..591 run one
#define LN2 0.69314718055994530942

typedef unsigned long long ull;

__device__ double g_scratch[BB];
__device__ unsigned int g_count = 0;
__device__ int g_len[BB];
__device__ int g_perm[BB];

__device__ __forceinline__ ull pack2f(float a, float b) {
    ull r;
    asm("mov.b64 %0, {%1, %2};" : "=l"(r) : "f"(a), "f"(b));
    return r;
}
__device__ __forceinline__ void unpack2f(ull v, float& lo, float& hi) {
    asm("mov.b64 {%0, %1}, %2;" : "=f"(lo), "=f"(hi) : "l"(v));
}
__device__ __forceinline__ void fma2(ull& acc, ull a, ull b) {
    asm("fma.rn.f32x2 %0, %1, %2, %0;" : "+l"(acc) : "l"(a), "l"(b));
}
__device__ __forceinline__ ull add2(ull a, ull b) {
    ull r;
    asm("add.rn.f32x2 %0, %1, %2;" : "=l"(r) : "l"(a), "l"(b));
    return r;
}
__device__ __forceinline__ float hsum2(ull a, ull b) {
    ull u = add2(a, b);
    float lo, hi;
    unpack2f(u, lo, hi);
    return lo + hi;
}
__device__ __forceinline__ float warp_sum_f(float v) {
    #pragma unroll
    for (int o = 16; o; o >>= 1) v += __shfl_xor_sync(FULL, v, o);
    return v;
}

// ---------- fused prepass: lengths (binary search on monotone mask) + sort ----------
extern "C" __global__ void __launch_bounds__(1024)
prep_kernel(const float* __restrict__ mask) {
    const int b = threadIdx.x;          // 1024 threads = 1024 batches
    int lo = 0, hi = SS;
    #pragma unroll
    for (int it = 0; it < 9; it++) {    // 2^9 = 512
        int mid = (lo + hi) >> 1;
        bool one = __ldg(&mask[b * SS + mid]) > 0.5f;
        lo = one ? mid : lo;
        hi = one ? hi : mid;
    }
    const int len = lo + 1;
    g_len[b] = len;

    __shared__ int hist[SS + 1];
    if (threadIdx.x <= SS) hist[threadIdx.x] = 0;
    __syncthreads();
    atomicAdd(&hist[len], 1);
    __syncthreads();
    if (threadIdx.x == 0) {
        int acc = 0;
        for (int i = 0; i <= SS; i++) { int c = hist[i]; hist[i] = acc; acc += c; }
    }
    __syncthreads();
    int r = atomicAdd(&hist[len], 1);
    g_perm[r] = b;                      // ascending by length
}

// One recurrence step. Writer-side combine: lane l and l+16 own the same 3
// columns; each sums its 24-row half, then shfl.xor(16)+add merges halves.
// Single combined p array in smem (hi half stores to a shadow region).
// Rescale every 4 steps by exact power-of-2 (exponent bits); esum is exact int.
#define STEPX(pA_, pB_, pC_, exA_, exB_, exC_, RBOFF_, WBOFF_, DORESC_, t_) do { \
    const unsigned rb_ = pbufb + (RBOFF_);                                      \
    const unsigned wb_ = pbufb + (WBOFF_);                                      \
    float ceA_ = __expf(exA_);                                                  \
    float ceB_ = __expf(exB_);                                                  \
    float ceC_ = __expf(exC_);                                                  \
    if (DORESC_ && (((t_) & 3) == 0)) {                                         \
        float r0_;                                                              \
        asm volatile("ld.shared.f32 %0, [%1];" : "=f"(r0_) : "r"(rb_));         \
        int e_ = ((__float_as_int(r0_) >> 23) & 0xFF) - 127;                    \
        float sc_ = __int_as_float((127 - e_) << 23);                           \
        ceA_ *= sc_; ceB_ *= sc_; ceC_ *= sc_;                                  \
        esum += e_;                                                             \
    }                                                                           \
    ull a0_ = 0ull, a1_ = 0ull, b0_ = 0ull, b1_ = 0ull, c0_ = 0ull, c1_ = 0ull; \
    const unsigned lo_ = rb_ + rb4;                                             \
    _Pragma("unroll")                                                           \
    for (int c = 0; c < 3; c++) {                                               \
        ull P0, P1, P2, P3;                                                     \
        asm volatile("ld.shared.v2.u64 {%0, %1}, [%2];"                         \
            : "=l"(P0), "=l"(P1) : "r"(lo_ + c * 32));                          \
        asm volatile("ld.shared.v2.u64 {%0, %1}, [%2];"                         \
            : "=l"(P2), "=l"(P3) : "r"(lo_ + c * 32 + 16));                     \
        fma2(a0_, P0, EA[4*c  ]); fma2(b0_, P0, EB[4*c  ]); fma2(c0_, P0, EC[4*c  ]); \
        fma2(a1_, P1, EA[4*c+1]); fma2(b1_, P1, EB[4*c+1]); fma2(c1_, P1, EC[4*c+1]); \
        fma2(a0_, P2, EA[4*c+2]); fma2(b0_, P2, EB[4*c+2]); fma2(c0_, P2, EC[4*c+2]); \
        fma2(a1_, P3, EA[4*c+3]); fma2(b1_, P3, EB[4*c+3]); fma2(c1_, P3, EC[4*c+3]); \
    }                                                                           \
    float qA_ = hsum2(a0_, a1_) * ceA_;                                         \
    float qB_ = hsum2(b0_, b1_) * ceB_;                                         \
    float qC_ = hsum2(c0_, c1_) * ceC_;                                         \
    qA_ += __shfl_xor_sync(FULL, qA_, 16);                                      \
    qB_ += __shfl_xor_sync(FULL, qB_, 16);                                      \
    qC_ += __shfl_xor_sync(FULL, qC_, 16);                                      \
    pA_ = qA_; pB_ = qB_; pC_ = qC_;                                            \
    const unsigned st_ = wb_ + stoff;                                           \
    asm volatile("st.shared.f32 [%0], %1;" :: "r"(st_),       "f"(qA_));        \
    asm volatile("st.shared.f32 [%0], %1;" :: "r"(st_ + 64),  "f"(qB_));        \
    asm volatile("st.shared.f32 [%0], %1;" :: "r"(st_ + 128), "f"(qC_));        \
} while (0)

// clamped 3-column emission load for step s (branchless, always in-bounds)
#define LD3(s_, x_, y_, z_) do {                                                \
    int r_ = min((s_), len - 1);                                                \
    const float* p_ = emp + (long)r_ * TT;                                      \
    x_ = __ldg(p_ + cA); y_ = __ldg(p_ + cB); z_ = __ldg(p_ + cC);              \
} while (0)

// 148 blocks x 128 threads: 1 CTA/SM, 1 warp/SMSP. Warp k runs perm[1023-k]
// (long) then, if k < NPAIR, perm[k] (short): pair sums ~= 513 steps for all.
extern "C" __global__ void __launch_bounds__(128)
crf_kernel(const float* __restrict__ em,      // [B,S,T]
           const int*   __restrict__ tags,    // [B,S]
           const float* __restrict__ trans,   // [T,T]
           const float* __restrict__ startt,  // [T]
           const float* __restrict__ endt,    // [T]
           float* __restrict__ out)
{
    const int lane = threadIdx.x & 31;
    const int wid  = threadIdx.x >> 5;
    const int k    = blockIdx.x * 4 + wid;      // 0..591

    // [warp][parity][128 floats]: bytes 0..192 = combined p (48), 256..448 = hi shadow
    __shared__ __align__(16) float p_buf[4][2][128];

    const int j     = lane & 15;
    const int half  = lane >> 4;
    const int rbase = half * 24;
    const unsigned rb4 = (unsigned)(rbase * 4);
    const int cA = j, cB = j + 16, cC = j + 32;

    // ---- E = exp(transitions): this lane's 24 rows x 3 columns ----
    ull EA[12], EB[12], EC[12];
    #pragma unroll
    for (int kk = 0; kk < 12; kk++) {
        int r = rbase + 2 * kk;
        EA[kk] = pack2f(__expf(__ldg(&trans[r * TT + cA])),
                        __expf(__ldg(&trans[(r + 1) * TT + cA])));
        EB[kk] = pack2f(__expf(__ldg(&trans[r * TT + cB])),
                        __expf(__ldg(&trans[(r + 1) * TT + cB])));
        EC[kk] = pack2f(__expf(__ldg(&trans[r * TT + cC])),
                        __expf(__ldg(&trans[(r + 1) * TT + cC])));
    }
    const float eeA = __expf(__ldg(&endt[cA]));
    const float eeB = __expf(__ldg(&endt[cB]));
    const float eeC = __expf(__ldg(&endt[cC]));

    const unsigned pbufb = (unsigned)__cvta_generic_to_shared(&p_buf[wid][0][0]);
    const unsigned stoff = (unsigned)(half * 256 + j * 4);   // hi half -> shadow

    const int npass = (k < NPAIR) ? 2 : 1;
    #pragma unroll 1
    for (int pass = 0; pass < npass; pass++) {
        const int b   = (pass == 0) ? g_perm[BB - 1 - k] : g_perm[k];
        const int len = g_len[b];
        const float* emp = em + (long)b * SS * TT;

        // ---- gold path score ----
        float gold;
        {
            float g = 0.f;
            const long eb = (long)b * SS * TT;
            #pragma unroll 4
            for (int it = 0; it < SS / 32; it++) {
                int t = lane + it * 32;
                if (t < len) {
                    int tg = tags[b * SS + t];
                    if (t == 0) g += __ldg(&startt[tg]) + __ldg(&em[eb + tg]);
                    else {
                        int tp = tags[b * SS + t - 1];
                        g += __ldg(&trans[tg * TT + tp]) + __ldg(&em[eb + (long)t * TT + tg]);
                    }
                    if (t == len - 1) g += __ldg(&endt[tg]);
                }
            }
            gold = warp_sum_f(g);
        }

        // ---- init at t = 0: combined p on ALL lanes (both halves identical) ----
        float pA, pB, pC, sref;
        int esum = 0;
        {
            float a  = __ldg(&startt[cA]) + emp[cA];
            float bb = __ldg(&startt[cB]) + emp[cB];
            float cc = __ldg(&startt[cC]) + emp[cC];
            sref = __shfl_sync(FULL, a, 0);
            pA = __expf(a - sref);
            pB = __expf(bb - sref);
            pC = __expf(cc - sref);
            unsigned s0 = pbufb + stoff;   // parity 0 (hi half writes shadow)
            asm volatile("st.shared.f32 [%0], %1;" :: "r"(s0),       "f"(pA));
            asm volatile("st.shared.f32 [%0], %1;" :: "r"(s0 + 64),  "f"(pB));
            asm volatile("st.shared.f32 [%0], %1;" :: "r"(s0 + 128), "f"(pC));
        }

        // ---- emission register pipeline: rows t .. t+3 in e0..e3 ----
        float e0A, e0B, e0C, e1A, e1B, e1C, e2A, e2B, e2C, e3A, e3B, e3C;
        LD3(1, e0A, e0B, e0C);
        LD3(2, e1A, e1B, e1C);
        LD3(3, e2A, e2B, e2C);
        LD3(4, e3A, e3B, e3C);

        int t = 1;   // stays odd at loop top -> static parities in the body
        #pragma unroll 1
        for (; t + 3 < len; t += 4) {
            float n0A, n0B, n0C, n1A, n1B, n1C, n2A, n2B, n2C, n3A, n3B, n3C;
            LD3(t + 4, n0A, n0B, n0C);
            LD3(t + 5, n1A, n1B, n1C);
            LD3(t + 6, n2A, n2B, n2C);
            LD3(t + 7, n3A, n3B, n3C);

            STEPX(pA, pB, pC, e0A, e0B, e0C,   0u, 512u, 0, t);
            STEPX(pA, pB, pC, e1A, e1B, e1C, 512u,   0u, 1, t + 1);
            STEPX(pA, pB, pC, e2A, e2B, e2C,   0u, 512u, 0, t + 2);
            STEPX(pA, pB, pC, e3A, e3B, e3C, 512u,   0u, 1, t + 3);

            e0A = n0A; e0B = n0B; e0C = n0C;
            e1A = n1A; e1B = n1B; e1C = n1C;
            e2A = n2A; e2B = n2B; e2C = n2C;
            e3A = n3A; e3B = n3B; e3C = n3C;
        }
        if (t < len) { STEPX(pA, pB, pC, e0A, e0B, e0C,   0u, 512u, 0, t); t++; }
        if (t < len) { STEPX(pA, pB, pC, e1A, e1B, e1C, 512u,   0u, 1, t); t++; }
        if (t < len) { STEPX(pA, pB, pC, e2A, e2B, e2C,   0u, 512u, 0, t); t++; }

        // ---- final: fwd = sref + esum*ln2 + log(sum_c p_c * exp(end_c)) ----
        {
            float v = pA * eeA + pB * eeB + pC * eeC;
            float ssum = warp_sum_f(v) * 0.5f;   // both halves hold combined p
            if (lane == 0)
                g_scratch[b] = (double)sref + (double)esum * LN2
                             + (double)__logf(ssum) - (double)gold;
        }
    }

    // ---- fused mean: last block reduces ----
    __syncthreads();
    __shared__ bool is_last;
    if (threadIdx.x == 0) {
        __threadfence();
        unsigned r = atomicAdd(&g_count, 1u);
        is_last = (r == gridDim.x - 1);
    }
    __syncthreads();
    if (is_last) {
        __threadfence();
        double s = 0.0;
        for (int i = threadIdx.x; i < BB; i += 128) s += g_scratch[i];
        __shared__ double sh[128];
        sh[threadIdx.x] = s;
        __syncthreads();
        #pragma unroll
        for (int o = 64; o; o >>= 1) {
            if (threadIdx.x < o) sh[threadIdx.x] += sh[threadIdx.x + o];
            __syncthreads();
        }
        if (threadIdx.x == 0) {
            out[0] = (float)(sh[0] / (double)BB);
            g_count = 0;   // reset for next graph replay
        }
    }
}

extern "C" void kernel_launch(void* const* d_in, const int* in_sizes, int n_in,
                              void* d_out, int out_size) {
    const float* em     = (const float*)d_in[0];
    const int*   tags   = (const int*)d_in[1];
    const float* mask   = (const float*)d_in[2];
    const float* trans  = (const float*)d_in[3];
    const float* startt = (const float*)d_in[4];
    const float* endt   = (const float*)d_in[5];
    float* out = (float*)d_out;

    prep_kernel<<<1, 1024>>>(mask);
    crf_kernel<<<148, 128>>>(em, tags, trans, startt, endt, out);
}